// round 3
// baseline (speedup 1.0000x reference)
#include <cuda_runtime.h>
#include <math.h>

// Problem constants
#define B_    32
#define C_    128
#define HW_   4096     // 64*64
#define NWIN  2048     // B * (64/8)*(64/8)
#define HID_  512

// ---------------- scratch (device globals; small footprint) ------------------
__device__ float g_skip[16777216];      // [B*H*W][128] token-major (b*4096+h*64+w)
__device__ float g_bias[16384];         // [4][64][64]

// ---------------- meta-network relative position bias ------------------------
__global__ void k_bias(const float* __restrict__ w1, const float* __restrict__ b1,
                       const float* __restrict__ w2, const float* __restrict__ b2) {
    int pair = blockIdx.x * 256 + threadIdx.x;   // 0..4095
    int q = pair >> 6, k = pair & 63;
    float d0 = (float)((q >> 3) - (k >> 3));
    float d1 = (float)((q & 7)  - (k & 7));
    float r0 = copysignf(log1pf(fabsf(d0)), d0);
    float r1 = copysignf(log1pf(fabsf(d1)), d1);
    float a0 = 0.f, a1 = 0.f, a2 = 0.f, a3 = 0.f;
    for (int j = 0; j < 256; j++) {
        float h = fmaf(r0, w1[j], fmaf(r1, w1[256 + j], b1[j]));
        h = fmaxf(h, 0.f);
        a0 += h * w2[j*4+0]; a1 += h * w2[j*4+1];
        a2 += h * w2[j*4+2]; a3 += h * w2[j*4+3];
    }
    g_bias[0*4096 + pair] = a0 + b2[0];
    g_bias[1*4096 + pair] = a1 + b2[1];
    g_bias[2*4096 + pair] = a2 + b2[2];
    g_bias[3*4096 + pair] = a3 + b2[3];
}

// =============================================================================
// Mega-kernel 1: window gather + QKV GEMM + 4-head cosine attention +
//                proj GEMM + LN1 + residual  ->  g_skip
// One block per window. 256 threads.
// Dynamic smem layout (floats):
//   As  [0, 8320)        : x gather K-major [128][65]; later att out K-major;
//                          later outS (x residual staging [64][129.. uses 8320])
//   QKV [8320, 33152)    : [64 tokens][388] (q 0:128, k 128:256, v 256:384)
//                          later: Bp proj weights [128][128] (16384) + Ps [64][130]
//   BsQ [33152, 41344)   : qkv weight panel [128][64]; later S scores [64][65]
// total 41344 floats = 165376 bytes
// =============================================================================
#define SM_ATTN 165376

__global__ void k_attnproj(const float* __restrict__ x,
                           const float* __restrict__ qkv_w, const float* __restrict__ qkv_b,
                           const float* __restrict__ proj_w, const float* __restrict__ proj_b,
                           const float* __restrict__ tau,
                           const float* __restrict__ g, const float* __restrict__ bt) {
    extern __shared__ float sm[];
    float* As  = sm;
    float* QKV = sm + 8320;
    float* BsQ = sm + 33152;
    __shared__ float qn[64], kn[64], mu[64], rs[64];

    int bw = blockIdx.x;
    int b = bw >> 6, wi = bw & 63, whi = wi >> 3, wwi = wi & 7;
    int tid = threadIdx.x;
    int tn = tid & 15, tm = tid >> 4;

    // ---- phase 0: gather shifted window from NCHW x, K-major ----------------
    for (int e = tid; e < 8192; e += 256) {
        int k = e >> 6, m = e & 63;
        int hp = (whi*8 + (m >> 3) + 4) & 63;
        int wp = (wwi*8 + (m & 7)  + 4) & 63;
        As[k*65 + m] = x[((size_t)(b*C_ + k))*HW_ + hp*64 + wp];
    }

    // ---- phase 1: QKV GEMM [64,128]@[128,384] into QKV smem -----------------
    for (int n0 = 0; n0 < 384; n0 += 64) {
        __syncthreads();
        for (int e = tid; e < 8192; e += 256) {
            int n = e & 63, k = e >> 6;
            BsQ[k*64 + n] = qkv_w[(size_t)k*384 + n0 + n];
        }
        __syncthreads();
        float acc[4][4] = {};
#pragma unroll 4
        for (int k = 0; k < 128; k++) {
            float4 bv = *(const float4*)(BsQ + k*64 + 4*tn);
            float a0 = As[k*65 + 4*tm + 0];
            float a1 = As[k*65 + 4*tm + 1];
            float a2 = As[k*65 + 4*tm + 2];
            float a3 = As[k*65 + 4*tm + 3];
            acc[0][0]+=a0*bv.x; acc[0][1]+=a0*bv.y; acc[0][2]+=a0*bv.z; acc[0][3]+=a0*bv.w;
            acc[1][0]+=a1*bv.x; acc[1][1]+=a1*bv.y; acc[1][2]+=a1*bv.z; acc[1][3]+=a1*bv.w;
            acc[2][0]+=a2*bv.x; acc[2][1]+=a2*bv.y; acc[2][2]+=a2*bv.z; acc[2][3]+=a2*bv.w;
            acc[3][0]+=a3*bv.x; acc[3][1]+=a3*bv.y; acc[3][2]+=a3*bv.z; acc[3][3]+=a3*bv.w;
        }
        float4 bb = *(const float4*)(qkv_b + n0 + 4*tn);
#pragma unroll
        for (int i = 0; i < 4; i++) {
            float4 o;
            o.x = acc[i][0] + bb.x; o.y = acc[i][1] + bb.y;
            o.z = acc[i][2] + bb.z; o.w = acc[i][3] + bb.w;
            *(float4*)(QKV + (4*tm + i)*388 + n0 + 4*tn) = o;
        }
    }

    // ---- phase 2: attention, 4 heads sequential, from QKV smem --------------
    float* S = BsQ;                         // [64][65]
    for (int h = 0; h < 4; h++) {
        __syncthreads();                    // QKV ready / S reusable
        if (tid < 128) {
            int t = tid & 63;
            const float* p = QKV + t*388 + ((tid < 64) ? 0 : 128) + h*32;
            float s = 0.f;
#pragma unroll
            for (int d = 0; d < 32; d++) s += p[d]*p[d];
            float nv = sqrtf(s);
            if (tid < 64) qn[t] = nv; else kn[t] = nv;
        }
        __syncthreads();
        float inv_tau = 1.f / fmaxf(tau[h], 0.01f);
        int kk = tid & 63;
        float kreg[32];
#pragma unroll
        for (int d = 0; d < 32; d++) kreg[d] = QKV[kk*388 + 128 + h*32 + d];
        float knv = kn[kk];
        int regk = ((whi == 7) ? ((kk >> 3) < 4 ? 1 : 2) : 0) * 3
                 + ((wwi == 7) ? ((kk & 7)  < 4 ? 1 : 2) : 0);
        const float* bias_h = g_bias + h*4096;
        int qbase = tid >> 6;
#pragma unroll
        for (int i = 0; i < 16; i++) {
            int q = qbase + 4*i;
            float dot = 0.f;
#pragma unroll
            for (int d = 0; d < 32; d++) dot += QKV[q*388 + h*32 + d]*kreg[d];
            float sc = dot / fmaxf(qn[q]*knv, 1e-6f) * inv_tau;
            sc += bias_h[q*64 + kk];
            int rq = ((whi == 7) ? ((q >> 3) < 4 ? 1 : 2) : 0) * 3
                   + ((wwi == 7) ? ((q & 7)  < 4 ? 1 : 2) : 0);
            if (rq != regk) sc -= 100.f;
            S[q*65 + kk] = sc;
        }
        __syncthreads();
        int warp = tid >> 5, lane = tid & 31;
        for (int r = warp*8; r < warp*8 + 8; r++) {
            float v0 = S[r*65 + lane], v1 = S[r*65 + lane + 32];
            float m = fmaxf(v0, v1);
#pragma unroll
            for (int o = 16; o; o >>= 1) m = fmaxf(m, __shfl_xor_sync(0xffffffffu, m, o));
            float e0 = __expf(v0 - m), e1 = __expf(v1 - m);
            float s = e0 + e1;
#pragma unroll
            for (int o = 16; o; o >>= 1) s += __shfl_xor_sync(0xffffffffu, s, o);
            float inv = 1.f / s;
            S[r*65 + lane]      = e0 * inv;
            S[r*65 + lane + 32] = e1 * inv;
        }
        __syncthreads();
        int dd = tid & 31, qb = tid >> 5;
#pragma unroll
        for (int i = 0; i < 8; i++) {
            int q = qb + 8*i;
            float a = 0.f;
#pragma unroll
            for (int k = 0; k < 64; k++) a += S[q*65 + k] * QKV[k*388 + 256 + h*32 + dd];
            As[(h*32 + dd)*65 + q] = a;      // att output, K-major
        }
    }

    // ---- phase 3: proj GEMM [64,128]@[128,128] + LN1 + residual -------------
    __syncthreads();
    float* Bp = QKV;                        // [128][128]
    float* Ps = QKV + 16384;                // [64][130]
    for (int e = tid; e < 16384; e += 256) {
        int n = e & 127, k = e >> 7;
        Bp[k*128 + n] = proj_w[k*128 + n];
    }
    __syncthreads();
    float acc[4][8] = {};
#pragma unroll 2
    for (int k = 0; k < 128; k++) {
        float4 b0 = *(const float4*)(Bp + k*128 + 8*tn);
        float4 b1 = *(const float4*)(Bp + k*128 + 8*tn + 4);
        float a0 = As[k*65 + 4*tm + 0];
        float a1 = As[k*65 + 4*tm + 1];
        float a2 = As[k*65 + 4*tm + 2];
        float a3 = As[k*65 + 4*tm + 3];
        acc[0][0]+=a0*b0.x; acc[0][1]+=a0*b0.y; acc[0][2]+=a0*b0.z; acc[0][3]+=a0*b0.w;
        acc[0][4]+=a0*b1.x; acc[0][5]+=a0*b1.y; acc[0][6]+=a0*b1.z; acc[0][7]+=a0*b1.w;
        acc[1][0]+=a1*b0.x; acc[1][1]+=a1*b0.y; acc[1][2]+=a1*b0.z; acc[1][3]+=a1*b0.w;
        acc[1][4]+=a1*b1.x; acc[1][5]+=a1*b1.y; acc[1][6]+=a1*b1.z; acc[1][7]+=a1*b1.w;
        acc[2][0]+=a2*b0.x; acc[2][1]+=a2*b0.y; acc[2][2]+=a2*b0.z; acc[2][3]+=a2*b0.w;
        acc[2][4]+=a2*b1.x; acc[2][5]+=a2*b1.y; acc[2][6]+=a2*b1.z; acc[2][7]+=a2*b1.w;
        acc[3][0]+=a3*b0.x; acc[3][1]+=a3*b0.y; acc[3][2]+=a3*b0.z; acc[3][3]+=a3*b0.w;
        acc[3][4]+=a3*b1.x; acc[3][5]+=a3*b1.y; acc[3][6]+=a3*b1.z; acc[3][7]+=a3*b1.w;
    }
    __syncthreads();                        // As reads done -> reuse as outS
    float* outS = As;                       // [64][129]
#pragma unroll
    for (int i = 0; i < 4; i++) {
        int r = 4*tm + i;
#pragma unroll
        for (int j = 0; j < 8; j++)
            Ps[r*130 + 8*tn + j] = acc[i][j] + proj_b[8*tn + j];
    }
    for (int e = tid; e < 8192; e += 256) { // stage x residual (coalesced read)
        int k = e >> 6, r = e & 63;
        int hp = (whi*8 + (r >> 3) + 4) & 63;
        int wp = (wwi*8 + (r & 7)  + 4) & 63;
        outS[r*129 + k] = x[((size_t)(b*C_ + k))*HW_ + hp*64 + wp];
    }
    __syncthreads();
    int warp = tid >> 5, lane = tid & 31;
    for (int r = warp*8; r < warp*8 + 8; r++) {
        float s = 0.f, s2 = 0.f;
        for (int c = lane; c < 128; c += 32) {
            float v = Ps[r*130 + c];
            s += v; s2 += v*v;
        }
#pragma unroll
        for (int o = 16; o; o >>= 1) {
            s  += __shfl_xor_sync(0xffffffffu, s,  o);
            s2 += __shfl_xor_sync(0xffffffffu, s2, o);
        }
        if (lane == 0) {
            float m = s * (1.f/128.f);
            mu[r] = m;
            rs[r] = rsqrtf(s2 * (1.f/128.f) - m*m + 1e-5f);
        }
    }
    __syncthreads();
    for (int e = tid; e < 8192; e += 256) {
        int r = e >> 7, c = e & 127;
        int hp = (whi*8 + (r >> 3) + 4) & 63;
        int wp = (wwi*8 + (r & 7)  + 4) & 63;
        size_t pix = (size_t)b*HW_ + hp*64 + wp;
        float v = (Ps[r*130 + c] - mu[r]) * rs[r] * g[c] + bt[c];
        g_skip[pix*C_ + c] = outS[r*129 + c] + v;
    }
}

// =============================================================================
// Mega-kernel 2: FFN1 + GELU + FFN2 + LN2 + residual + NCHW transpose -> out
// One block per 64 consecutive tokens (one image row). 256 threads.
// Dynamic smem layout (floats):
//   As [0, 8320)       : skip tile K-major [128][65] (kept for residual)
//   Hs [8320, 41600)   : hidden transposed [512][65]; later Ps [64][130]
//   Bs [41600, 49920)  : weight panel [128][64]; later outS [64][130]
// total 49920 floats = 199680 bytes
// =============================================================================
#define SM_FFN 199680

__global__ void k_ffn(const float* __restrict__ w1, const float* __restrict__ b1,
                      const float* __restrict__ w2, const float* __restrict__ b2,
                      const float* __restrict__ g, const float* __restrict__ bt,
                      float* __restrict__ out) {
    extern __shared__ float sm[];
    float* As = sm;
    float* Hs = sm + 8320;
    float* Bs = sm + 41600;
    __shared__ float mu[64], rs[64];

    int blk = blockIdx.x;
    int row0 = blk * 64;
    int tid = threadIdx.x;
    int tn = tid & 15, tm = tid >> 4;

    // load skip tile K-major
    for (int e = tid; e < 8192; e += 256) {
        int m = e >> 7, k = e & 127;
        As[k*65 + m] = g_skip[(size_t)(row0 + m)*C_ + k];
    }

    // ---- FFN1 + GELU, hidden stored transposed [n][m] -----------------------
    for (int n0 = 0; n0 < HID_; n0 += 64) {
        __syncthreads();
        for (int e = tid; e < 8192; e += 256) {
            int n = e & 63, k = e >> 6;
            Bs[k*64 + n] = w1[(size_t)k*HID_ + n0 + n];
        }
        __syncthreads();
        float acc[4][4] = {};
#pragma unroll 4
        for (int k = 0; k < 128; k++) {
            float4 bv = *(const float4*)(Bs + k*64 + 4*tn);
            float a0 = As[k*65 + 4*tm + 0];
            float a1 = As[k*65 + 4*tm + 1];
            float a2 = As[k*65 + 4*tm + 2];
            float a3 = As[k*65 + 4*tm + 3];
            acc[0][0]+=a0*bv.x; acc[0][1]+=a0*bv.y; acc[0][2]+=a0*bv.z; acc[0][3]+=a0*bv.w;
            acc[1][0]+=a1*bv.x; acc[1][1]+=a1*bv.y; acc[1][2]+=a1*bv.z; acc[1][3]+=a1*bv.w;
            acc[2][0]+=a2*bv.x; acc[2][1]+=a2*bv.y; acc[2][2]+=a2*bv.z; acc[2][3]+=a2*bv.w;
            acc[3][0]+=a3*bv.x; acc[3][1]+=a3*bv.y; acc[3][2]+=a3*bv.z; acc[3][3]+=a3*bv.w;
        }
        float4 bb = *(const float4*)(b1 + n0 + 4*tn);
        float bb4[4] = {bb.x, bb.y, bb.z, bb.w};
#pragma unroll
        for (int i = 0; i < 4; i++) {
            int row = 4*tm + i;
#pragma unroll
            for (int j = 0; j < 4; j++) {
                float v = acc[i][j] + bb4[j];
                v = 0.5f * v * (1.f + erff(v * 0.70710678118654752f));
                Hs[(n0 + 4*tn + j)*65 + row] = v;
            }
        }
    }

    // ---- FFN2 [64,512]@[512,128] --------------------------------------------
    float acc2[4][8] = {};
#pragma unroll
    for (int nh = 0; nh < 2; nh++) {
        for (int kp = 0; kp < 4; kp++) {
            __syncthreads();
            for (int e = tid; e < 8192; e += 256) {
                int n = e & 63, k = e >> 6;
                Bs[k*64 + n] = w2[(size_t)(kp*128 + k)*C_ + nh*64 + n];
            }
            __syncthreads();
#pragma unroll 4
            for (int k = 0; k < 128; k++) {
                float4 bv = *(const float4*)(Bs + k*64 + 4*tn);
                const float* hp = Hs + (kp*128 + k)*65 + 4*tm;
                float a0 = hp[0], a1 = hp[1], a2 = hp[2], a3 = hp[3];
                acc2[0][4*nh+0]+=a0*bv.x; acc2[0][4*nh+1]+=a0*bv.y; acc2[0][4*nh+2]+=a0*bv.z; acc2[0][4*nh+3]+=a0*bv.w;
                acc2[1][4*nh+0]+=a1*bv.x; acc2[1][4*nh+1]+=a1*bv.y; acc2[1][4*nh+2]+=a1*bv.z; acc2[1][4*nh+3]+=a1*bv.w;
                acc2[2][4*nh+0]+=a2*bv.x; acc2[2][4*nh+1]+=a2*bv.y; acc2[2][4*nh+2]+=a2*bv.z; acc2[2][4*nh+3]+=a2*bv.w;
                acc2[3][4*nh+0]+=a3*bv.x; acc2[3][4*nh+1]+=a3*bv.y; acc2[3][4*nh+2]+=a3*bv.z; acc2[3][4*nh+3]+=a3*bv.w;
            }
        }
    }
    __syncthreads();                        // Hs reads done -> reuse as Ps
    float* Ps = Hs;                         // [64][130]
#pragma unroll
    for (int i = 0; i < 4; i++) {
        int r = 4*tm + i;
#pragma unroll
        for (int nh = 0; nh < 2; nh++)
#pragma unroll
            for (int j = 0; j < 4; j++)
                Ps[r*130 + nh*64 + 4*tn + j] = acc2[i][4*nh+j] + b2[nh*64 + 4*tn + j];
    }
    __syncthreads();
    int warp = tid >> 5, lane = tid & 31;
    for (int r = warp*8; r < warp*8 + 8; r++) {
        float s = 0.f, s2 = 0.f;
        for (int c = lane; c < 128; c += 32) {
            float v = Ps[r*130 + c];
            s += v; s2 += v*v;
        }
#pragma unroll
        for (int o = 16; o; o >>= 1) {
            s  += __shfl_xor_sync(0xffffffffu, s,  o);
            s2 += __shfl_xor_sync(0xffffffffu, s2, o);
        }
        if (lane == 0) {
            float m = s * (1.f/128.f);
            mu[r] = m;
            rs[r] = rsqrtf(s2 * (1.f/128.f) - m*m + 1e-5f);
        }
    }
    __syncthreads();
    float* outS = Bs;                       // [64][130]
    for (int e = tid; e < 8192; e += 256) {
        int r = e >> 7, c = e & 127;
        float v = (Ps[r*130 + c] - mu[r]) * rs[r] * g[c] + bt[c];
        outS[r*130 + c] = As[c*65 + r] + v;
    }
    __syncthreads();
    int b = blk >> 6, hh = blk & 63;
    for (int e = tid; e < 8192; e += 256) {
        int c = e >> 6, r = e & 63;
        out[((size_t)(b*C_ + c))*HW_ + hh*64 + r] = outS[r*130 + c];
    }
}

// ---------------- launch ------------------------------------------------------
extern "C" void kernel_launch(void* const* d_in, const int* in_sizes, int n_in,
                              void* d_out, int out_size) {
    (void)in_sizes; (void)n_in; (void)out_size;
    const float* x      = (const float*)d_in[0];
    const float* qkv_w  = (const float*)d_in[1];
    const float* qkv_b  = (const float*)d_in[2];
    const float* proj_w = (const float*)d_in[3];
    const float* proj_b = (const float*)d_in[4];
    const float* mw1    = (const float*)d_in[5];
    const float* mb1    = (const float*)d_in[6];
    const float* mw2    = (const float*)d_in[7];
    const float* mb2    = (const float*)d_in[8];
    const float* tau    = (const float*)d_in[9];
    const float* ln1g   = (const float*)d_in[10];
    const float* ln1b   = (const float*)d_in[11];
    const float* ln2g   = (const float*)d_in[12];
    const float* ln2b   = (const float*)d_in[13];
    const float* fw1    = (const float*)d_in[14];
    const float* fb1    = (const float*)d_in[15];
    const float* fw2    = (const float*)d_in[16];
    const float* fb2    = (const float*)d_in[17];
    float* out = (float*)d_out;

    cudaFuncSetAttribute(k_attnproj, cudaFuncAttributeMaxDynamicSharedMemorySize, SM_ATTN);
    cudaFuncSetAttribute(k_ffn,      cudaFuncAttributeMaxDynamicSharedMemorySize, SM_FFN);

    k_bias<<<16, 256>>>(mw1, mb1, mw2, mb2);
    k_attnproj<<<NWIN, 256, SM_ATTN>>>(x, qkv_w, qkv_b, proj_w, proj_b, tau, ln1g, ln1b);
    k_ffn<<<NWIN, 256, SM_FFN>>>(fw1, fb1, fw2, fb2, ln2g, ln2b, out);
}

// round 5
// speedup vs baseline: 2.0177x; 2.0177x over previous
#include <cuda_runtime.h>
#include <math.h>
#include <stdint.h>

#define B_    32
#define C_    128
#define HW_   4096
#define NWIN  2048
#define HID_  512

__device__ float g_skip[16777216];      // [B*H*W][128] token-major
__device__ float g_bias[16384];         // [4][64][64]

// ---------------- helpers -----------------------------------------------------
__device__ __forceinline__ uint32_t f2tf(float f) {
    uint32_t u; asm("cvt.rna.tf32.f32 %0, %1;" : "=r"(u) : "f"(f)); return u;
}
__device__ __forceinline__ void mma8(float* d, uint32_t a0, uint32_t a1, uint32_t a2, uint32_t a3,
                                     uint32_t b0, uint32_t b1) {
    asm volatile("mma.sync.aligned.m16n8k8.row.col.f32.tf32.tf32.f32 "
        "{%0,%1,%2,%3}, {%4,%5,%6,%7}, {%8,%9}, {%0,%1,%2,%3};"
        : "+f"(d[0]), "+f"(d[1]), "+f"(d[2]), "+f"(d[3])
        : "r"(a0), "r"(a1), "r"(a2), "r"(a3), "r"(b0), "r"(b1));
}
__device__ __forceinline__ int region(int t, int whi, int wwi) {
    return ((whi == 7) ? (((t >> 3) < 4) ? 1 : 2) : 0) * 3
         + ((wwi == 7) ? (((t & 7)  < 4) ? 1 : 2) : 0);
}
__device__ __forceinline__ float gelu_exact(float v) {
    return 0.5f * v * (1.f + erff(v * 0.70710678118654752f));
}

// ---------------- meta-network relative position bias ------------------------
__global__ void k_bias(const float* __restrict__ w1, const float* __restrict__ b1,
                       const float* __restrict__ w2, const float* __restrict__ b2) {
    int t = threadIdx.x;
    int pair = blockIdx.x * 64 + (t >> 2);   // 0..4095
    int h = t & 3;
    int q = pair >> 6, k = pair & 63;
    float d0 = (float)((q >> 3) - (k >> 3));
    float d1 = (float)((q & 7)  - (k & 7));
    float r0 = copysignf(log1pf(fabsf(d0)), d0);
    float r1 = copysignf(log1pf(fabsf(d1)), d1);
    float a = 0.f;
    for (int j = 0; j < 256; j++) {
        float hv = fmaxf(fmaf(r0, w1[j], fmaf(r1, w1[256 + j], b1[j])), 0.f);
        a += hv * w2[j*4 + h];
    }
    g_bias[h*4096 + pair] = a + b2[h];
}

// =============================================================================
// Mega-kernel 1: gather + QKV mma + 4-head cosine attention (QK/SV mma) +
//                proj mma + LN1 + residual -> g_skip
// 256 threads/block, 1 block per window.
// Smem word map (uint32/float):
//   phase A: XT[128][72]@0, BS[128][72]@9216, QT[384][72]@18432
//   phase B: S fp32[64][65]@0, AT[128][72]@4608, QT live
//   phase C: AT live, BS2[128][72]@18432, PS fp32[64][130]@27648, OS fp32[64][130]@35968
// total 46080 words = 184320 bytes
// =============================================================================
#define SMA_BYTES 184320

__global__ void k_attnproj(const float* __restrict__ x,
                           const float* __restrict__ qkv_w, const float* __restrict__ qkv_b,
                           const float* __restrict__ proj_w, const float* __restrict__ proj_b,
                           const float* __restrict__ tau,
                           const float* __restrict__ g, const float* __restrict__ bt) {
    extern __shared__ uint32_t sm[];
    uint32_t* XT  = sm;
    uint32_t* BS  = sm + 9216;
    uint32_t* QT  = sm + 18432;
    float*    S   = (float*)sm;
    uint32_t* AT  = sm + 4608;
    uint32_t* BS2 = sm + 18432;
    float*    PS  = (float*)(sm + 27648);
    float*    OS  = (float*)(sm + 35968);
    __shared__ float qn[64], kn[64], mu[64], rs[64];

    int bw = blockIdx.x;
    int b = bw >> 6, wi = bw & 63, whi = wi >> 3, wwi = wi & 7;
    int tid = threadIdx.x;
    int warp = tid >> 5, lane = tid & 31;
    int gid = lane >> 2, tig = lane & 3;
    int m0 = (warp & 3) * 16;
    int ng = warp >> 2;

    // ---- phase 0: gather shifted window -> XT (tf32, [C][tok]) --------------
    for (int e = tid; e < 8192; e += 256) {
        int k = e >> 6, m = e & 63;
        int hp = (whi*8 + (m >> 3) + 4) & 63;
        int wp = (wwi*8 + (m & 7)  + 4) & 63;
        XT[k*72 + m] = f2tf(x[((size_t)(b*C_ + k))*HW_ + hp*64 + wp]);
    }

    // ---- phase 1: QKV mma, epilogue -> QT[feat][tok] + bias -----------------
    for (int n0 = 0; n0 < 384; n0 += 64) {
        __syncthreads();
        for (int e = tid; e < 8192; e += 256) {
            int n = e & 63, k = e >> 6;
            BS[k*72 + n] = f2tf(qkv_w[(size_t)k*384 + n0 + n]);
        }
        __syncthreads();
        float acc[4][4] = {};
        for (int ks = 0; ks < 16; ks++) {
            int kb = ks*8;
            uint32_t a0 = XT[(kb+tig)*72 + m0+gid];
            uint32_t a1 = XT[(kb+tig)*72 + m0+gid+8];
            uint32_t a2 = XT[(kb+4+tig)*72 + m0+gid];
            uint32_t a3 = XT[(kb+4+tig)*72 + m0+gid+8];
#pragma unroll
            for (int j = 0; j < 4; j++) {
                int nb = ng*32 + j*8;
                mma8(acc[j], a0,a1,a2,a3,
                     BS[(kb+tig)*72 + nb+gid], BS[(kb+4+tig)*72 + nb+gid]);
            }
        }
#pragma unroll
        for (int j = 0; j < 4; j++) {
            int c0 = n0 + ng*32 + j*8 + 2*tig;
            int r  = m0 + gid;
            QT[(c0  )*72 + r  ] = f2tf(acc[j][0] + qkv_b[c0]);
            QT[(c0+1)*72 + r  ] = f2tf(acc[j][1] + qkv_b[c0+1]);
            QT[(c0  )*72 + r+8] = f2tf(acc[j][2] + qkv_b[c0]);
            QT[(c0+1)*72 + r+8] = f2tf(acc[j][3] + qkv_b[c0+1]);
        }
    }

    // ---- phase 2: attention, 4 heads -----------------------------------------
    for (int h = 0; h < 4; h++) {
        __syncthreads();                      // QT ready / S reusable
        if (tid < 128) {
            int t = tid & 63;
            const uint32_t* p = QT + (((tid < 64) ? 0 : 128) + h*32)*72 + t;
            float s = 0.f;
#pragma unroll
            for (int d = 0; d < 32; d++) { float v = __uint_as_float(p[d*72]); s += v*v; }
            float nv = sqrtf(s);
            if (tid < 64) qn[t] = nv; else kn[t] = nv;
        }
        __syncthreads();
        float inv_tau = 1.f / fmaxf(tau[h], 0.01f);
        const uint32_t* Qh = QT + (h*32)*72;
        const uint32_t* Kh = QT + (128 + h*32)*72;
        float acc[4][4] = {};
#pragma unroll
        for (int ks = 0; ks < 4; ks++) {
            int kb = ks*8;
            uint32_t a0 = Qh[(kb+tig)*72 + m0+gid];
            uint32_t a1 = Qh[(kb+tig)*72 + m0+gid+8];
            uint32_t a2 = Qh[(kb+4+tig)*72 + m0+gid];
            uint32_t a3 = Qh[(kb+4+tig)*72 + m0+gid+8];
#pragma unroll
            for (int j = 0; j < 4; j++) {
                int nb = ng*32 + j*8;
                mma8(acc[j], a0,a1,a2,a3,
                     Kh[(kb+tig)*72 + nb+gid], Kh[(kb+4+tig)*72 + nb+gid]);
            }
        }
        const float* bias_h = g_bias + h*4096;
        int r = m0 + gid;
        int rg0 = region(r, whi, wwi), rg1 = region(r+8, whi, wwi);
        float q0 = qn[r], q1 = qn[r+8];
#pragma unroll
        for (int j = 0; j < 4; j++) {
            int cc = ng*32 + j*8 + 2*tig;
#pragma unroll
            for (int u = 0; u < 2; u++) {
                int c = cc + u;
                float kv = kn[c];
                int rgc = region(c, whi, wwi);
                float s0 = acc[j][u]   / fmaxf(q0*kv, 1e-6f) * inv_tau + bias_h[r*64 + c];
                float s1 = acc[j][2+u] / fmaxf(q1*kv, 1e-6f) * inv_tau + bias_h[(r+8)*64 + c];
                if (rg0 != rgc) s0 -= 100.f;
                if (rg1 != rgc) s1 -= 100.f;
                S[r*65 + c]     = s0;
                S[(r+8)*65 + c] = s1;
            }
        }
        __syncthreads();
        for (int rr = warp*8; rr < warp*8 + 8; rr++) {
            float v0 = S[rr*65 + lane], v1 = S[rr*65 + lane + 32];
            float mx = fmaxf(v0, v1);
#pragma unroll
            for (int o = 16; o; o >>= 1) mx = fmaxf(mx, __shfl_xor_sync(~0u, mx, o));
            float e0 = __expf(v0 - mx), e1 = __expf(v1 - mx);
            float ssum = e0 + e1;
#pragma unroll
            for (int o = 16; o; o >>= 1) ssum += __shfl_xor_sync(~0u, ssum, o);
            float inv = 1.f / ssum;
            S[rr*65 + lane]      = __uint_as_float(f2tf(e0 * inv));
            S[rr*65 + lane + 32] = __uint_as_float(f2tf(e1 * inv));
        }
        __syncthreads();
        // SV: out^T = V^T @ S^T  (M=32 dims, N=64 q, K=64 keys) -> AT[feat][tok]
        const uint32_t* Vh = QT + (256 + h*32)*72;
        int m0v = (warp & 1) * 16;
        int nq0 = (warp >> 1) * 16;
        float acs[2][4] = {};
#pragma unroll
        for (int ks = 0; ks < 8; ks++) {
            int kb = ks*8;
            uint32_t a0 = Vh[(m0v+gid  )*72 + kb+tig];
            uint32_t a1 = Vh[(m0v+gid+8)*72 + kb+tig];
            uint32_t a2 = Vh[(m0v+gid  )*72 + kb+4+tig];
            uint32_t a3 = Vh[(m0v+gid+8)*72 + kb+4+tig];
#pragma unroll
            for (int j = 0; j < 2; j++) {
                int nb = nq0 + j*8;
                mma8(acs[j], a0,a1,a2,a3,
                     __float_as_uint(S[(nb+gid)*65 + kb+tig]),
                     __float_as_uint(S[(nb+gid)*65 + kb+4+tig]));
            }
        }
#pragma unroll
        for (int j = 0; j < 2; j++) {
            int qc = nq0 + j*8 + 2*tig;
            int dr = m0v + gid;
            AT[(h*32 + dr  )*72 + qc  ] = f2tf(acs[j][0]);
            AT[(h*32 + dr  )*72 + qc+1] = f2tf(acs[j][1]);
            AT[(h*32 + dr+8)*72 + qc  ] = f2tf(acs[j][2]);
            AT[(h*32 + dr+8)*72 + qc+1] = f2tf(acs[j][3]);
        }
    }

    // ---- phase 3: proj mma + LN1 + residual ---------------------------------
    __syncthreads();                          // all warps done reading QT/S
    for (int n0 = 0; n0 < 128; n0 += 64) {
        for (int e = tid; e < 8192; e += 256) {
            int n = e & 63, k = e >> 6;
            BS2[k*72 + n] = f2tf(proj_w[k*128 + n0 + n]);
        }
        __syncthreads();
        float acc[4][4] = {};
        for (int ks = 0; ks < 16; ks++) {
            int kb = ks*8;
            uint32_t a0 = AT[(kb+tig)*72 + m0+gid];
            uint32_t a1 = AT[(kb+tig)*72 + m0+gid+8];
            uint32_t a2 = AT[(kb+4+tig)*72 + m0+gid];
            uint32_t a3 = AT[(kb+4+tig)*72 + m0+gid+8];
#pragma unroll
            for (int j = 0; j < 4; j++) {
                int nb = ng*32 + j*8;
                mma8(acc[j], a0,a1,a2,a3,
                     BS2[(kb+tig)*72 + nb+gid], BS2[(kb+4+tig)*72 + nb+gid]);
            }
        }
#pragma unroll
        for (int j = 0; j < 4; j++) {
            int c0 = n0 + ng*32 + j*8 + 2*tig;
            int r = m0 + gid;
            PS[r*130 + c0]       = acc[j][0] + proj_b[c0];
            PS[r*130 + c0+1]     = acc[j][1] + proj_b[c0+1];
            PS[(r+8)*130 + c0]   = acc[j][2] + proj_b[c0];
            PS[(r+8)*130 + c0+1] = acc[j][3] + proj_b[c0+1];
        }
        __syncthreads();
    }
    // residual x staging (exact fp32)
    for (int e = tid; e < 8192; e += 256) {
        int k = e >> 6, m = e & 63;
        int hp = (whi*8 + (m >> 3) + 4) & 63;
        int wp = (wwi*8 + (m & 7)  + 4) & 63;
        OS[m*130 + k] = x[((size_t)(b*C_ + k))*HW_ + hp*64 + wp];
    }
    for (int rr = warp*8; rr < warp*8 + 8; rr++) {
        float s = 0.f, s2 = 0.f;
        for (int c = lane; c < 128; c += 32) { float v = PS[rr*130 + c]; s += v; s2 += v*v; }
#pragma unroll
        for (int o = 16; o; o >>= 1) { s += __shfl_xor_sync(~0u, s, o); s2 += __shfl_xor_sync(~0u, s2, o); }
        if (lane == 0) {
            float m_ = s * (1.f/128.f);
            mu[rr] = m_;
            rs[rr] = rsqrtf(s2 * (1.f/128.f) - m_*m_ + 1e-5f);
        }
    }
    __syncthreads();
    for (int e = tid; e < 8192; e += 256) {
        int r = e >> 7, c = e & 127;
        int hp = (whi*8 + (r >> 3) + 4) & 63;
        int wp = (wwi*8 + (r & 7)  + 4) & 63;
        size_t pix = (size_t)b*HW_ + hp*64 + wp;
        float v = (PS[r*130 + c] - mu[r]) * rs[r] * g[c] + bt[c];
        g_skip[pix*C_ + c] = OS[r*130 + c] + v;
    }
}

// =============================================================================
// Mega-kernel 2: FFN1 mma + GELU + FFN2 mma (register-accumulated over panels)
//                + LN2 + residual + NCHW transpose -> out
// 256 threads/block, 1 block per 64 tokens. Smem 110592 B -> 2 CTAs/SM.
// Smem word map: ASK[128][72]@0, BS1[128][72]@9216, HT[64][72]@18432,
//                BS2[64][72]@23040;  epilogue: PS@9216, OS@18432
// =============================================================================
#define SMF_BYTES 110592

__global__ void __launch_bounds__(256, 2)
k_ffn(const float* __restrict__ w1, const float* __restrict__ b1,
      const float* __restrict__ w2, const float* __restrict__ b2,
      const float* __restrict__ g, const float* __restrict__ bt,
      float* __restrict__ out) {
    extern __shared__ uint32_t sm[];
    uint32_t* ASK = sm;
    uint32_t* BS1 = sm + 9216;
    uint32_t* HT  = sm + 18432;
    uint32_t* BS2 = sm + 23040;
    float*    PS  = (float*)(sm + 9216);
    float*    OS  = (float*)(sm + 18432);
    __shared__ float mu[64], rs[64];

    int row0 = blockIdx.x * 64;
    int tid = threadIdx.x;
    int warp = tid >> 5, lane = tid & 31;
    int gid = lane >> 2, tig = lane & 3;
    int m0 = (warp & 3) * 16;
    int ng = warp >> 2;

    for (int e = tid; e < 8192; e += 256) {
        int m = e >> 7, c = e & 127;
        ASK[c*72 + m] = f2tf(g_skip[(size_t)(row0 + m)*C_ + c]);
    }

    float acc2[2][4][4] = {};
    for (int p = 0; p < 8; p++) {
        int n0 = p*64;
        __syncthreads();
        for (int e = tid; e < 8192; e += 256) {
            int n = e & 63, k = e >> 6;
            BS1[k*72 + n] = f2tf(w1[(size_t)k*HID_ + n0 + n]);
        }
        __syncthreads();
        float acc[4][4] = {};
        for (int ks = 0; ks < 16; ks++) {
            int kb = ks*8;
            uint32_t a0 = ASK[(kb+tig)*72 + m0+gid];
            uint32_t a1 = ASK[(kb+tig)*72 + m0+gid+8];
            uint32_t a2 = ASK[(kb+4+tig)*72 + m0+gid];
            uint32_t a3 = ASK[(kb+4+tig)*72 + m0+gid+8];
#pragma unroll
            for (int j = 0; j < 4; j++) {
                int nb = ng*32 + j*8;
                mma8(acc[j], a0,a1,a2,a3,
                     BS1[(kb+tig)*72 + nb+gid], BS1[(kb+4+tig)*72 + nb+gid]);
            }
        }
        __syncthreads();   // prev panel's FFN2 done reading HT (ensured below), write now
#pragma unroll
        for (int j = 0; j < 4; j++) {
            int cl = ng*32 + j*8 + 2*tig;
            int r = m0 + gid;
            float bb0 = b1[n0 + cl], bb1 = b1[n0 + cl + 1];
            HT[(cl  )*72 + r  ] = f2tf(gelu_exact(acc[j][0] + bb0));
            HT[(cl+1)*72 + r  ] = f2tf(gelu_exact(acc[j][1] + bb1));
            HT[(cl  )*72 + r+8] = f2tf(gelu_exact(acc[j][2] + bb0));
            HT[(cl+1)*72 + r+8] = f2tf(gelu_exact(acc[j][3] + bb1));
        }
        __syncthreads();
        for (int nh = 0; nh < 2; nh++) {
            for (int e = tid; e < 4096; e += 256) {
                int n = e & 63, k = e >> 6;
                BS2[k*72 + n] = f2tf(w2[(size_t)(n0 + k)*C_ + nh*64 + n]);
            }
            __syncthreads();
            for (int ks = 0; ks < 8; ks++) {
                int kb = ks*8;
                uint32_t a0 = HT[(kb+tig)*72 + m0+gid];
                uint32_t a1 = HT[(kb+tig)*72 + m0+gid+8];
                uint32_t a2 = HT[(kb+4+tig)*72 + m0+gid];
                uint32_t a3 = HT[(kb+4+tig)*72 + m0+gid+8];
#pragma unroll
                for (int j = 0; j < 4; j++) {
                    int nb = ng*32 + j*8;
                    mma8(acc2[nh][j], a0,a1,a2,a3,
                         BS2[(kb+tig)*72 + nb+gid], BS2[(kb+4+tig)*72 + nb+gid]);
                }
            }
            __syncthreads();
        }
    }

    // epilogue: bias -> PS, LN2, residual, transpose out
#pragma unroll
    for (int nh = 0; nh < 2; nh++)
#pragma unroll
    for (int j = 0; j < 4; j++) {
        int c0 = nh*64 + ng*32 + j*8 + 2*tig;
        int r = m0 + gid;
        PS[r*130 + c0]       = acc2[nh][j][0] + b2[c0];
        PS[r*130 + c0+1]     = acc2[nh][j][1] + b2[c0+1];
        PS[(r+8)*130 + c0]   = acc2[nh][j][2] + b2[c0];
        PS[(r+8)*130 + c0+1] = acc2[nh][j][3] + b2[c0+1];
    }
    __syncthreads();
    for (int rr = warp*8; rr < warp*8 + 8; rr++) {
        float s = 0.f, s2 = 0.f;
        for (int c = lane; c < 128; c += 32) { float v = PS[rr*130 + c]; s += v; s2 += v*v; }
#pragma unroll
        for (int o = 16; o; o >>= 1) { s += __shfl_xor_sync(~0u, s, o); s2 += __shfl_xor_sync(~0u, s2, o); }
        if (lane == 0) {
            float m_ = s * (1.f/128.f);
            mu[rr] = m_;
            rs[rr] = rsqrtf(s2 * (1.f/128.f) - m_*m_ + 1e-5f);
        }
    }
    __syncthreads();
    for (int e = tid; e < 8192; e += 256) {
        int r = e >> 7, c = e & 127;
        float v = (PS[r*130 + c] - mu[r]) * rs[r] * g[c] + bt[c];
        OS[r*130 + c] = g_skip[(size_t)(row0 + r)*C_ + c] + v;
    }
    __syncthreads();
    int b = blockIdx.x >> 6, hh = blockIdx.x & 63;
    for (int e = tid; e < 8192; e += 256) {
        int c = e >> 6, r = e & 63;
        out[((size_t)(b*C_ + c))*HW_ + hh*64 + r] = OS[r*130 + c];
    }
}

// ---------------- launch ------------------------------------------------------
extern "C" void kernel_launch(void* const* d_in, const int* in_sizes, int n_in,
                              void* d_out, int out_size) {
    (void)in_sizes; (void)n_in; (void)out_size;
    const float* x      = (const float*)d_in[0];
    const float* qkv_w  = (const float*)d_in[1];
    const float* qkv_b  = (const float*)d_in[2];
    const float* proj_w = (const float*)d_in[3];
    const float* proj_b = (const float*)d_in[4];
    const float* mw1    = (const float*)d_in[5];
    const float* mb1    = (const float*)d_in[6];
    const float* mw2    = (const float*)d_in[7];
    const float* mb2    = (const float*)d_in[8];
    const float* tau    = (const float*)d_in[9];
    const float* ln1g   = (const float*)d_in[10];
    const float* ln1b   = (const float*)d_in[11];
    const float* ln2g   = (const float*)d_in[12];
    const float* ln2b   = (const float*)d_in[13];
    const float* fw1    = (const float*)d_in[14];
    const float* fb1    = (const float*)d_in[15];
    const float* fw2    = (const float*)d_in[16];
    const float* fb2    = (const float*)d_in[17];
    float* out = (float*)d_out;

    cudaFuncSetAttribute(k_attnproj, cudaFuncAttributeMaxDynamicSharedMemorySize, SMA_BYTES);
    cudaFuncSetAttribute(k_ffn,      cudaFuncAttributeMaxDynamicSharedMemorySize, SMF_BYTES);

    k_bias<<<64, 256>>>(mw1, mb1, mw2, mb2);
    k_attnproj<<<NWIN, 256, SMA_BYTES>>>(x, qkv_w, qkv_b, proj_w, proj_b, tau, ln1g, ln1b);
    k_ffn<<<NWIN, 256, SMF_BYTES>>>(fw1, fb1, fw2, fb2, ln2g, ln2b, out);
}

// round 9
// speedup vs baseline: 2.8469x; 1.4110x over previous
#include <cuda_runtime.h>
#include <math.h>
#include <stdint.h>

#define B_    32
#define C_    128
#define HW_   4096
#define NWIN  2048
#define HID_  512

__device__ float g_skip[16777216];      // [B*H*W][128] token-major
__device__ float g_bias[16384];         // [4][64][64]

// ---------------- helpers -----------------------------------------------------
__device__ __forceinline__ uint32_t f2tf(float f) {
    uint32_t u; asm("cvt.rna.tf32.f32 %0, %1;" : "=r"(u) : "f"(f)); return u;
}
__device__ __forceinline__ void mma8(float* d, uint32_t a0, uint32_t a1, uint32_t a2, uint32_t a3,
                                     uint32_t b0, uint32_t b1) {
    asm volatile("mma.sync.aligned.m16n8k8.row.col.f32.tf32.tf32.f32 "
        "{%0,%1,%2,%3}, {%4,%5,%6,%7}, {%8,%9}, {%0,%1,%2,%3};"
        : "+f"(d[0]), "+f"(d[1]), "+f"(d[2]), "+f"(d[3])
        : "r"(a0), "r"(a1), "r"(a2), "r"(a3), "r"(b0), "r"(b1));
}
__device__ __forceinline__ int region(int t, int whi, int wwi) {
    return ((whi == 7) ? (((t >> 3) < 4) ? 1 : 2) : 0) * 3
         + ((wwi == 7) ? (((t & 7)  < 4) ? 1 : 2) : 0);
}
__device__ __forceinline__ float gelu_exact(float v) {
    return 0.5f * v * (1.f + erff(v * 0.70710678118654752f));
}

// ---------------- meta-network relative position bias ------------------------
__global__ void k_bias(const float* __restrict__ w1, const float* __restrict__ b1,
                       const float* __restrict__ w2, const float* __restrict__ b2) {
    int t = threadIdx.x;
    int pair = blockIdx.x * 64 + (t >> 2);
    int h = t & 3;
    int q = pair >> 6, k = pair & 63;
    float d0 = (float)((q >> 3) - (k >> 3));
    float d1 = (float)((q & 7)  - (k & 7));
    float r0 = copysignf(log1pf(fabsf(d0)), d0);
    float r1 = copysignf(log1pf(fabsf(d1)), d1);
    float a = 0.f;
    for (int j = 0; j < 256; j++) {
        float hv = fmaxf(fmaf(r0, w1[j], fmaf(r1, w1[256 + j], b1[j])), 0.f);
        a += hv * w2[j*4 + h];
    }
    g_bias[h*4096 + pair] = a + b2[h];
}

// =============================================================================
// Mega-kernel 1: 512 threads/block, 1 block/window.
// Smem words: XT[128][72]@0, BS[128][136]@9216, QT[384][72]@26624 -> 54272 w
// phase B: S0[64][68]@0, S1@4352, AT[128][72]@9216 (alias BS), QT live
// phase C: BS2[128][136]@26624 (alias QT), PS[64][130]@0, OS[64][130]@44032
// =============================================================================
#define SMA_BYTES 217088

__global__ void __launch_bounds__(512)
k_attnproj(const float* __restrict__ x,
           const float* __restrict__ qkv_w, const float* __restrict__ qkv_b,
           const float* __restrict__ proj_w, const float* __restrict__ proj_b,
           const float* __restrict__ tau,
           const float* __restrict__ g, const float* __restrict__ bt) {
    extern __shared__ uint32_t sm[];
    uint32_t* XT  = sm;
    uint32_t* BS  = sm + 9216;
    uint32_t* QT  = sm + 26624;
    float*    S0  = (float*)sm;
    float*    S1  = (float*)(sm + 4352);
    uint32_t* AT  = sm + 9216;
    uint32_t* BS2 = sm + 26624;
    float*    PS  = (float*)sm;
    float*    OS  = (float*)(sm + 44032);
    __shared__ float qn[2][64], kn[2][64], mu[64], rs[64];

    int bw = blockIdx.x;
    int b = bw >> 6, wi = bw & 63, whi = wi >> 3, wwi = wi & 7;
    int tid = threadIdx.x;
    int warp = tid >> 5, lane = tid & 31;
    int gid = lane >> 2, tig = lane & 3;

    // ---- phase 0: gather shifted window -> XT[c][tok] -----------------------
    for (int e = tid; e < 8192; e += 512) {
        int k = e >> 6, m = e & 63;
        int hp = (whi*8 + (m >> 3) + 4) & 63;
        int wp = (wwi*8 + (m & 7)  + 4) & 63;
        XT[k*72 + m] = f2tf(x[((size_t)(b*C_ + k))*HW_ + hp*64 + wp]);
    }

    // ---- phase 1: QKV, 3 passes of N=128, prefetched weights ----------------
    {
        int mw = warp & 3, m0 = mw*16, ng = warp >> 2;   // ng 0..3
        float4 wr[8];
#pragma unroll
        for (int i = 0; i < 8; i++) {
            int f = tid + i*512, k = f >> 5, n = (f & 31)*4;
            wr[i] = *(const float4*)(qkv_w + (size_t)k*384 + n);
        }
        for (int pass = 0; pass < 3; pass++) {
            __syncthreads();
#pragma unroll
            for (int i = 0; i < 8; i++) {
                int f = tid + i*512, k = f >> 5, n = (f & 31)*4;
                uint32_t* d = BS + k*136 + n;
                d[0]=f2tf(wr[i].x); d[1]=f2tf(wr[i].y); d[2]=f2tf(wr[i].z); d[3]=f2tf(wr[i].w);
            }
            __syncthreads();
            if (pass < 2) {
                int n0n = (pass+1)*128;
#pragma unroll
                for (int i = 0; i < 8; i++) {
                    int f = tid + i*512, k = f >> 5, n = (f & 31)*4;
                    wr[i] = *(const float4*)(qkv_w + (size_t)k*384 + n0n + n);
                }
            }
            float acc[4][4] = {};
            for (int ks = 0; ks < 16; ks++) {
                int kb = ks*8;
                uint32_t a0 = XT[(kb+tig)*72 + m0+gid];
                uint32_t a1 = XT[(kb+tig)*72 + m0+gid+8];
                uint32_t a2 = XT[(kb+4+tig)*72 + m0+gid];
                uint32_t a3 = XT[(kb+4+tig)*72 + m0+gid+8];
#pragma unroll
                for (int j = 0; j < 4; j++) {
                    int nb = ng*32 + j*8;
                    mma8(acc[j], a0,a1,a2,a3,
                         BS[(kb+tig)*136 + nb+gid], BS[(kb+4+tig)*136 + nb+gid]);
                }
            }
            int n0 = pass*128;
#pragma unroll
            for (int j = 0; j < 4; j++) {
                int c0 = n0 + ng*32 + j*8 + 2*tig;
                int r  = m0 + gid;
                QT[(c0  )*72 + r  ] = f2tf(acc[j][0] + qkv_b[c0]);
                QT[(c0+1)*72 + r  ] = f2tf(acc[j][1] + qkv_b[c0+1]);
                QT[(c0  )*72 + r+8] = f2tf(acc[j][2] + qkv_b[c0]);
                QT[(c0+1)*72 + r+8] = f2tf(acc[j][3] + qkv_b[c0+1]);
            }
        }
    }

    // ---- phase 2: attention, 2 heads in parallel ----------------------------
    {
        int hp = warp >> 3;              // 0 or 1 -> head half
        int wv = warp & 7;               // virtual warp in half
        float* Sh = hp ? S1 : S0;
        for (int hb = 0; hb < 4; hb += 2) {
            int h = hb + hp;
            __syncthreads();             // QT ready / S free / AT free
            int t256 = tid & 255;
            int half = tid >> 8;
            if (t256 < 128) {
                int t = t256 & 63;
                int hh = hb + half;
                const uint32_t* p = QT + (((t256 < 64) ? 0 : 128) + hh*32)*72 + t;
                float s = 0.f;
#pragma unroll
                for (int d = 0; d < 32; d++) { float v = __uint_as_float(p[d*72]); s += v*v; }
                if (t256 < 64) qn[half][t] = sqrtf(s); else kn[half][t] = sqrtf(s);
            }
            __syncthreads();
            float inv_tau = 1.f / fmaxf(tau[h], 0.01f);
            const uint32_t* Qh = QT + (h*32)*72;
            const uint32_t* Kh = QT + (128 + h*32)*72;
            int m0s = (wv & 3)*16;
            int ngh = wv >> 2;
            float acc[4][4] = {};
#pragma unroll
            for (int ks = 0; ks < 4; ks++) {
                int kb = ks*8;
                uint32_t a0 = Qh[(kb+tig)*72 + m0s+gid];
                uint32_t a1 = Qh[(kb+tig)*72 + m0s+gid+8];
                uint32_t a2 = Qh[(kb+4+tig)*72 + m0s+gid];
                uint32_t a3 = Qh[(kb+4+tig)*72 + m0s+gid+8];
#pragma unroll
                for (int j = 0; j < 4; j++) {
                    int nb = ngh*32 + j*8;
                    mma8(acc[j], a0,a1,a2,a3,
                         Kh[(kb+tig)*72 + nb+gid], Kh[(kb+4+tig)*72 + nb+gid]);
                }
            }
            const float* bias_h = g_bias + h*4096;
            int r = m0s + gid;
            int rg0 = region(r, whi, wwi), rg1 = region(r+8, whi, wwi);
            float q0 = qn[hp][r], q1 = qn[hp][r+8];
#pragma unroll
            for (int j = 0; j < 4; j++) {
                int cc = ngh*32 + j*8 + 2*tig;
#pragma unroll
                for (int u = 0; u < 2; u++) {
                    int c = cc + u;
                    float kv = kn[hp][c];
                    int rgc = region(c, whi, wwi);
                    float s0 = acc[j][u]   / fmaxf(q0*kv, 1e-6f) * inv_tau + bias_h[r*64 + c];
                    float s1 = acc[j][2+u] / fmaxf(q1*kv, 1e-6f) * inv_tau + bias_h[(r+8)*64 + c];
                    if (rg0 != rgc) s0 -= 100.f;
                    if (rg1 != rgc) s1 -= 100.f;
                    Sh[r*68 + c]     = s0;
                    Sh[(r+8)*68 + c] = s1;
                }
            }
            __syncthreads();
            for (int rr = wv*8; rr < wv*8 + 8; rr++) {
                float v0 = Sh[rr*68 + lane], v1 = Sh[rr*68 + lane + 32];
                float mx = fmaxf(v0, v1);
#pragma unroll
                for (int o = 16; o; o >>= 1) mx = fmaxf(mx, __shfl_xor_sync(~0u, mx, o));
                float e0 = __expf(v0 - mx), e1 = __expf(v1 - mx);
                float ssum = e0 + e1;
#pragma unroll
                for (int o = 16; o; o >>= 1) ssum += __shfl_xor_sync(~0u, ssum, o);
                float inv = 1.f / ssum;
                Sh[rr*68 + lane]      = __uint_as_float(f2tf(e0 * inv));
                Sh[rr*68 + lane + 32] = __uint_as_float(f2tf(e1 * inv));
            }
            __syncthreads();
            const uint32_t* Vh = QT + (256 + h*32)*72;
            int m0v = (wv & 1)*16;
            int nq0 = (wv >> 1)*16;
            float acs[2][4] = {};
#pragma unroll
            for (int ks = 0; ks < 8; ks++) {
                int kb = ks*8;
                uint32_t a0 = Vh[(m0v+gid  )*72 + kb+tig];
                uint32_t a1 = Vh[(m0v+gid+8)*72 + kb+tig];
                uint32_t a2 = Vh[(m0v+gid  )*72 + kb+4+tig];
                uint32_t a3 = Vh[(m0v+gid+8)*72 + kb+4+tig];
#pragma unroll
                for (int j = 0; j < 2; j++) {
                    int nb = nq0 + j*8;
                    mma8(acs[j], a0,a1,a2,a3,
                         __float_as_uint(Sh[(nb+gid)*68 + kb+tig]),
                         __float_as_uint(Sh[(nb+gid)*68 + kb+4+tig]));
                }
            }
#pragma unroll
            for (int j = 0; j < 2; j++) {
                int qc = nq0 + j*8 + 2*tig;
                int dr = m0v + gid;
                AT[(h*32 + dr  )*72 + qc  ] = f2tf(acs[j][0]);
                AT[(h*32 + dr  )*72 + qc+1] = f2tf(acs[j][1]);
                AT[(h*32 + dr+8)*72 + qc  ] = f2tf(acs[j][2]);
                AT[(h*32 + dr+8)*72 + qc+1] = f2tf(acs[j][3]);
            }
        }
    }

    // ---- phase 3: proj (N=128 single pass) + LN1 + residual -----------------
    __syncthreads();                     // QT/S dead; AT complete
#pragma unroll
    for (int i = 0; i < 8; i++) {
        int f = tid + i*512, k = f >> 5, n = (f & 31)*4;
        float4 wv4 = *(const float4*)(proj_w + (size_t)k*128 + n);
        uint32_t* d = BS2 + k*136 + n;
        d[0]=f2tf(wv4.x); d[1]=f2tf(wv4.y); d[2]=f2tf(wv4.z); d[3]=f2tf(wv4.w);
    }
    __syncthreads();
    {
        int m0p = (warp & 3)*16, ngp = warp >> 2;
        float acc[4][4] = {};
        for (int ks = 0; ks < 16; ks++) {
            int kb = ks*8;
            uint32_t a0 = AT[(kb+tig)*72 + m0p+gid];
            uint32_t a1 = AT[(kb+tig)*72 + m0p+gid+8];
            uint32_t a2 = AT[(kb+4+tig)*72 + m0p+gid];
            uint32_t a3 = AT[(kb+4+tig)*72 + m0p+gid+8];
#pragma unroll
            for (int j = 0; j < 4; j++) {
                int nb = ngp*32 + j*8;
                mma8(acc[j], a0,a1,a2,a3,
                     BS2[(kb+tig)*136 + nb+gid], BS2[(kb+4+tig)*136 + nb+gid]);
            }
        }
#pragma unroll
        for (int j = 0; j < 4; j++) {
            int c0 = ngp*32 + j*8 + 2*tig;
            int r = m0p + gid;
            PS[r*130 + c0]       = acc[j][0] + proj_b[c0];
            PS[r*130 + c0+1]     = acc[j][1] + proj_b[c0+1];
            PS[(r+8)*130 + c0]   = acc[j][2] + proj_b[c0];
            PS[(r+8)*130 + c0+1] = acc[j][3] + proj_b[c0+1];
        }
    }
    __syncthreads();
    for (int rr = warp*4; rr < warp*4 + 4; rr++) {
        float s = 0.f, s2 = 0.f;
        for (int c = lane; c < 128; c += 32) { float v = PS[rr*130 + c]; s += v; s2 += v*v; }
#pragma unroll
        for (int o = 16; o; o >>= 1) { s += __shfl_xor_sync(~0u, s, o); s2 += __shfl_xor_sync(~0u, s2, o); }
        if (lane == 0) {
            float m_ = s * (1.f/128.f);
            mu[rr] = m_;
            rs[rr] = rsqrtf(s2 * (1.f/128.f) - m_*m_ + 1e-5f);
        }
    }
    for (int e = tid; e < 8192; e += 512) {
        int k = e >> 6, m = e & 63;
        int hh = (whi*8 + (m >> 3) + 4) & 63;
        int ww = (wwi*8 + (m & 7)  + 4) & 63;
        OS[m*130 + k] = x[((size_t)(b*C_ + k))*HW_ + hh*64 + ww];
    }
    __syncthreads();
    for (int e = tid; e < 8192; e += 512) {
        int r = e >> 7, c = e & 127;
        int hh = (whi*8 + (r >> 3) + 4) & 63;
        int ww = (wwi*8 + (r & 7)  + 4) & 63;
        size_t pix = (size_t)b*HW_ + hh*64 + ww;
        float v = (PS[r*130 + c] - mu[r]) * rs[r] * g[c] + bt[c];
        g_skip[pix*C_ + c] = OS[r*130 + c] + v;
    }
}

// =============================================================================
// Mega-kernel 2: 512 threads, 128 tokens/block (grid 1024).
// Smem words: ASK[128][136]@0, BS1[128][72]@17408, HT[64][136]@26624,
//             BS2[64][136]@35328  -> 44032 w = 176128 B
// epilogue: PS[128][130]@0, OS[128][130]@17408
// =============================================================================
#define SMF_BYTES 176128

__global__ void __launch_bounds__(512)
k_ffn(const float* __restrict__ w1, const float* __restrict__ b1,
      const float* __restrict__ w2, const float* __restrict__ b2,
      const float* __restrict__ g, const float* __restrict__ bt,
      float* __restrict__ out) {
    extern __shared__ uint32_t sm[];
    uint32_t* ASK = sm;
    uint32_t* BS1 = sm + 17408;
    uint32_t* HT  = sm + 26624;
    uint32_t* BS2 = sm + 35328;
    float*    PS  = (float*)sm;
    float*    OS  = (float*)(sm + 17408);
    __shared__ float mu[128], rs[128];

    int blk = blockIdx.x;
    int row0 = blk * 128;
    int tid = threadIdx.x;
    int warp = tid >> 5, lane = tid & 31;
    int gid = lane >> 2, tig = lane & 3;
    int m0 = (warp & 7)*16;              // 8 m-groups x 16 = 128 tokens
    int ng = warp >> 3;                  // 2 n-groups x 32

    // skip tile -> ASK[c][tok]
#pragma unroll
    for (int i = 0; i < 8; i++) {
        int f = tid + i*512, m = f >> 5, c4 = (f & 31)*4;
        float4 v = *(const float4*)(g_skip + (size_t)(row0 + m)*C_ + c4);
        ASK[(c4  )*136 + m] = f2tf(v.x);
        ASK[(c4+1)*136 + m] = f2tf(v.y);
        ASK[(c4+2)*136 + m] = f2tf(v.z);
        ASK[(c4+3)*136 + m] = f2tf(v.w);
    }

    float4 wr1[4], wr2[4];
#pragma unroll
    for (int i = 0; i < 4; i++) {
        int f = tid + i*512;
        { int k = f >> 4, n = (f & 15)*4; wr1[i] = *(const float4*)(w1 + (size_t)k*HID_ + n); }
        { int k = f >> 5, n = (f & 31)*4; wr2[i] = *(const float4*)(w2 + (size_t)k*C_ + n); }
    }

    float acc2[2][4][4] = {};
    for (int p = 0; p < 8; p++) {
        int n0 = p*64;
        __syncthreads();                 // BS/HT free (prev FFN2 done); ASK ready (p=0)
#pragma unroll
        for (int i = 0; i < 4; i++) {
            int f = tid + i*512;
            { int k = f >> 4, n = (f & 15)*4;
              uint32_t* d = BS1 + k*72 + n;
              d[0]=f2tf(wr1[i].x); d[1]=f2tf(wr1[i].y); d[2]=f2tf(wr1[i].z); d[3]=f2tf(wr1[i].w); }
            { int k = f >> 5, n = (f & 31)*4;
              uint32_t* d = BS2 + k*136 + n;
              d[0]=f2tf(wr2[i].x); d[1]=f2tf(wr2[i].y); d[2]=f2tf(wr2[i].z); d[3]=f2tf(wr2[i].w); }
        }
        __syncthreads();
        if (p < 7) {
            int n0n = (p+1)*64;
#pragma unroll
            for (int i = 0; i < 4; i++) {
                int f = tid + i*512;
                { int k = f >> 4, n = (f & 15)*4; wr1[i] = *(const float4*)(w1 + (size_t)k*HID_ + n0n + n); }
                { int k = f >> 5, n = (f & 31)*4; wr2[i] = *(const float4*)(w2 + (size_t)(n0n + k)*C_ + n); }
            }
        }
        // FFN1: [128 tok,128 c] @ [128 c,64 hid]
        float acc[4][4] = {};
        for (int ks = 0; ks < 16; ks++) {
            int kb = ks*8;
            uint32_t a0 = ASK[(kb+tig)*136 + m0+gid];
            uint32_t a1 = ASK[(kb+tig)*136 + m0+gid+8];
            uint32_t a2 = ASK[(kb+4+tig)*136 + m0+gid];
            uint32_t a3 = ASK[(kb+4+tig)*136 + m0+gid+8];
#pragma unroll
            for (int j = 0; j < 4; j++) {
                int nb = ng*32 + j*8;
                mma8(acc[j], a0,a1,a2,a3,
                     BS1[(kb+tig)*72 + nb+gid], BS1[(kb+4+tig)*72 + nb+gid]);
            }
        }
#pragma unroll
        for (int j = 0; j < 4; j++) {
            int cl = ng*32 + j*8 + 2*tig;
            int r = m0 + gid;
            float bb0 = b1[n0 + cl], bb1 = b1[n0 + cl + 1];
            HT[(cl  )*136 + r  ] = f2tf(gelu_exact(acc[j][0] + bb0));
            HT[(cl+1)*136 + r  ] = f2tf(gelu_exact(acc[j][1] + bb1));
            HT[(cl  )*136 + r+8] = f2tf(gelu_exact(acc[j][2] + bb0));
            HT[(cl+1)*136 + r+8] = f2tf(gelu_exact(acc[j][3] + bb1));
        }
        __syncthreads();
        // FFN2: [128 tok,64 hid] @ [64 hid,128 c], accumulate in regs
        for (int ks = 0; ks < 8; ks++) {
            int kb = ks*8;
            uint32_t a0 = HT[(kb+tig)*136 + m0+gid];
            uint32_t a1 = HT[(kb+tig)*136 + m0+gid+8];
            uint32_t a2 = HT[(kb+4+tig)*136 + m0+gid];
            uint32_t a3 = HT[(kb+4+tig)*136 + m0+gid+8];
#pragma unroll
            for (int nh = 0; nh < 2; nh++)
#pragma unroll
            for (int j = 0; j < 4; j++) {
                int nb = nh*64 + ng*32 + j*8;
                mma8(acc2[nh][j], a0,a1,a2,a3,
                     BS2[(kb+tig)*136 + nb+gid], BS2[(kb+4+tig)*136 + nb+gid]);
            }
        }
    }

    __syncthreads();                     // ASK dead -> PS, BS1/HT dead -> OS
#pragma unroll
    for (int nh = 0; nh < 2; nh++)
#pragma unroll
    for (int j = 0; j < 4; j++) {
        int c0 = nh*64 + ng*32 + j*8 + 2*tig;
        int r = m0 + gid;
        PS[r*130 + c0]       = acc2[nh][j][0] + b2[c0];
        PS[r*130 + c0+1]     = acc2[nh][j][1] + b2[c0+1];
        PS[(r+8)*130 + c0]   = acc2[nh][j][2] + b2[c0];
        PS[(r+8)*130 + c0+1] = acc2[nh][j][3] + b2[c0+1];
    }
    __syncthreads();
    for (int rr = warp*8; rr < warp*8 + 8; rr++) {
        float s = 0.f, s2 = 0.f;
        for (int c = lane; c < 128; c += 32) { float v = PS[rr*130 + c]; s += v; s2 += v*v; }
#pragma unroll
        for (int o = 16; o; o >>= 1) { s += __shfl_xor_sync(~0u, s, o); s2 += __shfl_xor_sync(~0u, s2, o); }
        if (lane == 0) {
            float m_ = s * (1.f/128.f);
            mu[rr] = m_;
            rs[rr] = rsqrtf(s2 * (1.f/128.f) - m_*m_ + 1e-5f);
        }
    }
    __syncthreads();
    for (int e = tid; e < 16384; e += 512) {
        int r = e >> 7, c = e & 127;
        float v = (PS[r*130 + c] - mu[r]) * rs[r] * g[c] + bt[c];
        OS[r*130 + c] = g_skip[(size_t)(row0 + r)*C_ + c] + v;
    }
    __syncthreads();
    int b = blk >> 5, poff = (blk & 31)*128;
    for (int e = tid; e < 16384; e += 512) {
        int c = e >> 7, r = e & 127;
        out[((size_t)(b*C_ + c))*HW_ + poff + r] = OS[r*130 + c];
    }
}

// ---------------- launch ------------------------------------------------------
extern "C" void kernel_launch(void* const* d_in, const int* in_sizes, int n_in,
                              void* d_out, int out_size) {
    (void)in_sizes; (void)n_in; (void)out_size;
    const float* x      = (const float*)d_in[0];
    const float* qkv_w  = (const float*)d_in[1];
    const float* qkv_b  = (const float*)d_in[2];
    const float* proj_w = (const float*)d_in[3];
    const float* proj_b = (const float*)d_in[4];
    const float* mw1    = (const float*)d_in[5];
    const float* mb1    = (const float*)d_in[6];
    const float* mw2    = (const float*)d_in[7];
    const float* mb2    = (const float*)d_in[8];
    const float* tau    = (const float*)d_in[9];
    const float* ln1g   = (const float*)d_in[10];
    const float* ln1b   = (const float*)d_in[11];
    const float* ln2g   = (const float*)d_in[12];
    const float* ln2b   = (const float*)d_in[13];
    const float* fw1    = (const float*)d_in[14];
    const float* fb1    = (const float*)d_in[15];
    const float* fw2    = (const float*)d_in[16];
    const float* fb2    = (const float*)d_in[17];
    float* out = (float*)d_out;

    cudaFuncSetAttribute(k_attnproj, cudaFuncAttributeMaxDynamicSharedMemorySize, SMA_BYTES);
    cudaFuncSetAttribute(k_ffn,      cudaFuncAttributeMaxDynamicSharedMemorySize, SMF_BYTES);

    k_bias<<<64, 256>>>(mw1, mb1, mw2, mb2);
    k_attnproj<<<NWIN, 512, SMA_BYTES>>>(x, qkv_w, qkv_b, proj_w, proj_b, tau, ln1g, ln1b);
    k_ffn<<<1024, 512, SMF_BYTES>>>(fw1, fb1, fw2, fb2, ln2g, ln2b, out);
}